// round 17
// baseline (speedup 1.0000x reference)
#include <cuda_runtime.h>
#include <cuda_bf16.h>

#define NMAX 50000
#define EMAX 800000
#define FEAT 256
#define HID 64
#define NOUT 40
#define SCAN_BLK 256
#define NBLKS ((NMAX + SCAN_BLK - 1) / SCAN_BLK)   // 196

#define TILE_R 256
#define KC 16
#define XS_STRIDE 20
#define W_STRIDE 72
#define HIST_BLKS 100

#define FLAG_AGG (1 << 30)
#define FLAG_PRE (2 << 30)
#define VAL_MASK (FLAG_AGG - 1)

// Scratch (device globals: allocation-free per harness rules)
__device__ int      g_cnt[NMAX + NBLKS];  // [0,NMAX): histogram; tail: scan states (zeroed together)
__device__ int      g_rank[EMAX];         // edge rank within dst list
__device__ int      g_off[NMAX + 1];      // final CSR offsets
__device__ int2     g_od[NMAX];           // packed (off_start, dinv-as-int)
__device__ int2     g_edge[EMAX];         // (src, nrm-as-int) per CSR slot
__device__ float    g_dinv[NMAX];
__device__ unsigned g_t1b[NMAX * (HID / 2)];   // x@W1, bf16x2 packed
__device__ float    g_h1[NMAX * HID];          // relu(agg1 + self + b1), fp32
__device__ unsigned g_t2b[NMAX * (NOUT / 2)];  // h1@W2, bf16x2 packed

__device__ __forceinline__ float tf32r(float f) {
    unsigned u;
    asm("cvt.rna.tf32.f32 %0, %1;" : "=r"(u) : "f"(f));
    return __uint_as_float(u);
}

__device__ __forceinline__ unsigned bf2(float lo, float hi) {
    __nv_bfloat162 b = __floats2bfloat162_rn(lo, hi);
    return *(unsigned*)&b;
}
__device__ __forceinline__ float2 unbf2(unsigned u) {
    return __bfloat1622float2(*(__nv_bfloat162*)&u);
}

__device__ __forceinline__ void mma_tf32(float* c, const unsigned* a,
                                         unsigned b0, unsigned b1) {
    asm("mma.sync.aligned.m16n8k8.row.col.f32.tf32.tf32.f32 "
        "{%0,%1,%2,%3}, {%4,%5,%6,%7}, {%8,%9}, {%0,%1,%2,%3};"
        : "+f"(c[0]), "+f"(c[1]), "+f"(c[2]), "+f"(c[3])
        : "r"(a[0]), "r"(a[1]), "r"(a[2]), "r"(a[3]), "r"(b0), "r"(b1));
}

__device__ __forceinline__ void cp16(unsigned daddr, const void* sptr, int zfill) {
    asm volatile("cp.async.cg.shared.global [%0], [%1], 16, %2;"
                 :: "r"(daddr), "l"(sptr), "r"(zfill) : "memory");
}

// ---- K1: gemm1 (tf32 mma, cp.async pipeline) + hist/rank (extra blocks) --

__global__ __launch_bounds__(256, 2) void gemm1_hist_kernel(
        const float* __restrict__ x, const float* __restrict__ W1,
        const int* __restrict__ dst, int n, int E, int ntiles) {
    if (blockIdx.x >= ntiles) {
        int e0 = (blockIdx.x - ntiles) * blockDim.x + threadIdx.x;
        int stride = HIST_BLKS * blockDim.x;
        for (int e = e0; e < E; e += stride)
            g_rank[e] = atomicAdd(&g_cnt[dst[e]], 1);
        return;
    }

    extern __shared__ float sm[];
    float* Wt  = sm;
    float* Xs0 = sm + FEAT * W_STRIDE;
    float* Xs1 = Xs0 + TILE_R * XS_STRIDE;

    const int tid  = threadIdx.x;
    const int warp = tid >> 5, lane = tid & 31;
    const int g = lane >> 2, t = lane & 3;
    const int base = blockIdx.x * TILE_R;

    {
        const float4* Wg = (const float4*)W1;
#pragma unroll
        for (int i = 0; i < 16; i++) {
            int f4 = i * 256 + tid;
            float4 v = Wg[f4];
            int flat = f4 * 4, k = flat >> 6, c0 = flat & 63;
            float* p = Wt + k * W_STRIDE + c0;
            p[0] = tf32r(v.x); p[1] = tf32r(v.y);
            p[2] = tf32r(v.z); p[3] = tf32r(v.w);
        }
    }

    unsigned xsu0 = (unsigned)__cvta_generic_to_shared(Xs0);
    unsigned xsu1 = (unsigned)__cvta_generic_to_shared(Xs1);

    float acc[2][8][4];
#pragma unroll
    for (int m = 0; m < 2; m++)
#pragma unroll
        for (int nt = 0; nt < 8; nt++)
#pragma unroll
            for (int q = 0; q < 4; q++) acc[m][nt][q] = 0.f;

    const int NCH = FEAT / KC;

#define STAGE(ch, bu)                                                          \
    {                                                                          \
        unsigned xb = (bu) ? xsu1 : xsu0;                                      \
        _Pragma("unroll")                                                      \
        for (int i = 0; i < 4; i++) {                                          \
            int f = i * 256 + tid;                                             \
            int row = f >> 2, kq = f & 3;                                      \
            int grow = base + row;                                             \
            bool ok = grow < n;                                                \
            const float* sp = x + (size_t)(ok ? grow : 0) * FEAT + (ch) * KC + kq * 4; \
            cp16(xb + (unsigned)(row * XS_STRIDE + kq * 4) * 4u, sp, ok ? 16 : 0); \
        }                                                                      \
        asm volatile("cp.async.commit_group;" ::: "memory");                   \
    }

    STAGE(0, 0);
    for (int ch = 0; ch < NCH; ch++) {
        int b = ch & 1;
        if (ch + 1 < NCH) {
            STAGE(ch + 1, b ^ 1);
            asm volatile("cp.async.wait_group 1;" ::: "memory");
        } else {
            asm volatile("cp.async.wait_group 0;" ::: "memory");
        }
        __syncthreads();

        const float* Xs = b ? Xs1 : Xs0;
        const float* xA = Xs + (warp * 32 + g) * XS_STRIDE;
#pragma unroll
        for (int ks = 0; ks < KC / 8; ks++) {
            int kk = ks * 8;
            unsigned a[2][4];
#pragma unroll
            for (int m = 0; m < 2; m++) {
                const float* xm = xA + m * 16 * XS_STRIDE;
                a[m][0] = __float_as_uint(xm[kk + t]);
                a[m][1] = __float_as_uint(xm[8 * XS_STRIDE + kk + t]);
                a[m][2] = __float_as_uint(xm[kk + t + 4]);
                a[m][3] = __float_as_uint(xm[8 * XS_STRIDE + kk + t + 4]);
            }
            int gk = ch * KC + kk;
            const float* wb  = Wt + (gk + t) * W_STRIDE + g;
            const float* wb4 = wb + 4 * W_STRIDE;
#pragma unroll
            for (int nt = 0; nt < 8; nt++) {
                unsigned b0 = __float_as_uint(wb[nt * 8]);
                unsigned b1 = __float_as_uint(wb4[nt * 8]);
                mma_tf32(acc[0][nt], a[0], b0, b1);
                mma_tf32(acc[1][nt], a[1], b0, b1);
            }
        }
        __syncthreads();
    }

#pragma unroll
    for (int m = 0; m < 2; m++) {
        int r0 = base + warp * 32 + m * 16 + g;
        int r1 = r0 + 8;
#pragma unroll
        for (int nt = 0; nt < 8; nt++) {
            if (r0 < n)
                g_t1b[(size_t)r0 * 32 + nt * 4 + t] = bf2(acc[m][nt][0], acc[m][nt][1]);
            if (r1 < n)
                g_t1b[(size_t)r1 * 32 + nt * 4 + t] = bf2(acc[m][nt][2], acc[m][nt][3]);
        }
    }
#undef STAGE
}

// ---- single-pass scan (decoupled lookback): off, dinv, od ---------------

__global__ void scan_kernel(int n) {
    __shared__ int s[SCAN_BLK];
    __shared__ int sh_exc;
    int* st = g_cnt + NMAX;   // per-block state, zeroed by memset
    int t = threadIdx.x, b = blockIdx.x;
    int i = b * SCAN_BLK + t;
    int v = (i < n) ? g_cnt[i] : 0;
    s[t] = v;
    __syncthreads();
#pragma unroll
    for (int o = 1; o < SCAN_BLK; o <<= 1) {
        int add = (t >= o) ? s[t - o] : 0;
        __syncthreads();
        s[t] += add;
        __syncthreads();
    }
    if (t == 0) {
        int total = s[SCAN_BLK - 1];
        int exc = 0;
        if (b == 0) {
            atomicExch(&st[0], total | FLAG_PRE);
        } else {
            atomicExch(&st[b], total | FLAG_AGG);
            int j = b - 1;
            while (true) {
                int f;
                do { f = atomicAdd(&st[j], 0); } while (f == 0);
                exc += f & VAL_MASK;
                if (f & FLAG_PRE) break;
                j--;
            }
            atomicExch(&st[b], (total + exc) | FLAG_PRE);
        }
        sh_exc = exc;
    }
    __syncthreads();
    int inc = s[t] + sh_exc;
    if (i < n) {
        g_off[i + 1] = inc;
        float dv = rsqrtf((float)v + 1.0f);
        g_dinv[i] = dv;
        g_od[i] = make_int2(inc - v, __float_as_int(dv));
    }
    if (i == 0) g_off[0] = 0;
}

// ---- fill CSR: atomic-free, 8 edges/thread ------------------------------

__global__ __launch_bounds__(256) void fill_kernel(const int* __restrict__ src,
                                                   const int* __restrict__ dst, int E) {
    int e0 = (blockIdx.x * blockDim.x + threadIdx.x) * 8;
    if (e0 >= E) return;
    int m = min(8, E - e0);
    int s[8], d[8], r[8];
#pragma unroll
    for (int j = 0; j < 8; j++) {
        int e = e0 + ((j < m) ? j : 0);
        s[j] = src[e]; d[j] = dst[e]; r[j] = g_rank[e];
    }
    int2 od[8]; float ds[8];
#pragma unroll
    for (int j = 0; j < 8; j++) { od[j] = g_od[d[j]]; ds[j] = g_dinv[s[j]]; }
#pragma unroll
    for (int j = 0; j < 8; j++) {
        if (j < m) {
            int slot = od[j].x + r[j];
            g_edge[slot] = make_int2(s[j], __float_as_int(ds[j] * __int_as_float(od[j].y)));
        }
    }
}

// ---- aggregate-1 + relu (bf16 t1, 4 edges per inner iter) ----------------

__global__ __launch_bounds__(256) void agg1_kernel(const float* __restrict__ b1, int n) {
    int node = (blockIdx.x * blockDim.x + threadIdx.x) >> 5;
    int lane = threadIdx.x & 31;
    int half = lane >> 4, q = lane & 15;
    if (node >= n) return;
    int beg = g_off[node], end = g_off[node + 1];

    float4 acc = make_float4(0.f, 0.f, 0.f, 0.f);
    for (int i = beg; i < end; i += 32) {
        int idx = i + lane;
        int s = 0; float w = 0.f;
        if (idx < end) { int2 ed = g_edge[idx]; s = ed.x; w = __int_as_float(ed.y); }
        int cnt = min(32, end - i);
        for (int j = 0; j < cnt; j += 4) {
            int j0 = j + half, j1 = j + 2 + half;
            int c0 = min(j0, cnt - 1), c1 = min(j1, cnt - 1);
            int ss0 = __shfl_sync(0xffffffffu, s, c0);
            int ss1 = __shfl_sync(0xffffffffu, s, c1);
            float w0 = __shfl_sync(0xffffffffu, w, c0);
            float w1 = __shfl_sync(0xffffffffu, w, c1);
            if (j0 >= cnt) w0 = 0.f;
            if (j1 >= cnt) w1 = 0.f;
            uint2 u0 = ((const uint2*)(g_t1b + (size_t)ss0 * 32))[q];
            uint2 u1 = ((const uint2*)(g_t1b + (size_t)ss1 * 32))[q];
            float2 a0 = unbf2(u0.x), b0 = unbf2(u0.y);
            float2 a1 = unbf2(u1.x), b1v = unbf2(u1.y);
            acc.x = fmaf(a0.x, w0, acc.x); acc.y = fmaf(a0.y, w0, acc.y);
            acc.z = fmaf(b0.x, w0, acc.z); acc.w = fmaf(b0.y, w0, acc.w);
            acc.x = fmaf(a1.x, w1, acc.x); acc.y = fmaf(a1.y, w1, acc.y);
            acc.z = fmaf(b1v.x, w1, acc.z); acc.w = fmaf(b1v.y, w1, acc.w);
        }
    }
    acc.x += __shfl_xor_sync(0xffffffffu, acc.x, 16);
    acc.y += __shfl_xor_sync(0xffffffffu, acc.y, 16);
    acc.z += __shfl_xor_sync(0xffffffffu, acc.z, 16);
    acc.w += __shfl_xor_sync(0xffffffffu, acc.w, 16);

    if (half == 0) {
        float d2 = g_dinv[node]; d2 *= d2;
        uint2 su = ((const uint2*)(g_t1b + (size_t)node * 32))[q];
        float2 sa = unbf2(su.x), sb = unbf2(su.y);
        float4 bb = ((const float4*)b1)[q];
        float4 r;
        r.x = fmaxf(fmaf(sa.x, d2, acc.x) + bb.x, 0.f);
        r.y = fmaxf(fmaf(sa.y, d2, acc.y) + bb.y, 0.f);
        r.z = fmaxf(fmaf(sb.x, d2, acc.z) + bb.z, 0.f);
        r.w = fmaxf(fmaf(sb.y, d2, acc.w) + bb.w, 0.f);
        ((float4*)(g_h1 + (size_t)node * HID))[q] = r;
    }
}

// ---- gemm2: t2 = h1 @ W2 (thread per row, W2 in smem, bf16 out) ----------

__global__ __launch_bounds__(256, 3) void gemm2_kernel(const float* __restrict__ W2, int n) {
    __shared__ float Ws[HID * NOUT];
    int row = blockIdx.x * 256 + threadIdx.x;
    for (int i = threadIdx.x; i < HID * NOUT; i += 256) Ws[i] = W2[i];
    __syncthreads();
    if (row >= n) return;

    float4 acc[10];
#pragma unroll
    for (int j = 0; j < 10; j++) acc[j] = make_float4(0.f, 0.f, 0.f, 0.f);

    const float4* hr = (const float4*)(g_h1 + (size_t)row * HID);
#pragma unroll 2
    for (int k4 = 0; k4 < 16; k4++) {
        float4 hv = hr[k4];
#pragma unroll
        for (int kk = 0; kk < 4; kk++) {
            float hs = (kk == 0) ? hv.x : (kk == 1) ? hv.y : (kk == 2) ? hv.z : hv.w;
            const float4* Wr = (const float4*)&Ws[(k4 * 4 + kk) * NOUT];
#pragma unroll
            for (int j = 0; j < 10; j++) {
                float4 w = Wr[j];
                acc[j].x = fmaf(hs, w.x, acc[j].x);
                acc[j].y = fmaf(hs, w.y, acc[j].y);
                acc[j].z = fmaf(hs, w.z, acc[j].z);
                acc[j].w = fmaf(hs, w.w, acc[j].w);
            }
        }
    }
    unsigned* out = g_t2b + (size_t)row * 20;
#pragma unroll
    for (int j = 0; j < 10; j++) {
        out[j * 2]     = bf2(acc[j].x, acc[j].y);
        out[j * 2 + 1] = bf2(acc[j].z, acc[j].w);
    }
}

// ---- aggregate-2 + log_softmax (bf16 t2, 4 edges per inner iter) ---------

__global__ __launch_bounds__(256) void agg2_kernel(const float* __restrict__ b2,
                                                   float* __restrict__ out, int n) {
    int node = (blockIdx.x * blockDim.x + threadIdx.x) >> 5;
    int lane = threadIdx.x & 31;
    int half = lane >> 4, q = lane & 15;
    if (node >= n) return;
    int beg = g_off[node], end = g_off[node + 1];

    float4 acc = make_float4(0.f, 0.f, 0.f, 0.f);
    for (int i = beg; i < end; i += 32) {
        int idx = i + lane;
        int s = 0; float w = 0.f;
        if (idx < end) { int2 ed = g_edge[idx]; s = ed.x; w = __int_as_float(ed.y); }
        int cnt = min(32, end - i);
        for (int j = 0; j < cnt; j += 4) {
            int j0 = j + half, j1 = j + 2 + half;
            int c0 = min(j0, cnt - 1), c1 = min(j1, cnt - 1);
            int ss0 = __shfl_sync(0xffffffffu, s, c0);
            int ss1 = __shfl_sync(0xffffffffu, s, c1);
            float w0 = __shfl_sync(0xffffffffu, w, c0);
            float w1 = __shfl_sync(0xffffffffu, w, c1);
            if (j0 >= cnt) w0 = 0.f;
            if (j1 >= cnt) w1 = 0.f;
            if (q < 10) {
                uint2 u0 = ((const uint2*)(g_t2b + (size_t)ss0 * 20))[q];
                uint2 u1 = ((const uint2*)(g_t2b + (size_t)ss1 * 20))[q];
                float2 a0 = unbf2(u0.x), b0 = unbf2(u0.y);
                float2 a1 = unbf2(u1.x), b1v = unbf2(u1.y);
                acc.x = fmaf(a0.x, w0, acc.x); acc.y = fmaf(a0.y, w0, acc.y);
                acc.z = fmaf(b0.x, w0, acc.z); acc.w = fmaf(b0.y, w0, acc.w);
                acc.x = fmaf(a1.x, w1, acc.x); acc.y = fmaf(a1.y, w1, acc.y);
                acc.z = fmaf(b1v.x, w1, acc.z); acc.w = fmaf(b1v.y, w1, acc.w);
            }
        }
    }
    acc.x += __shfl_xor_sync(0xffffffffu, acc.x, 16);
    acc.y += __shfl_xor_sync(0xffffffffu, acc.y, 16);
    acc.z += __shfl_xor_sync(0xffffffffu, acc.z, 16);
    acc.w += __shfl_xor_sync(0xffffffffu, acc.w, 16);

    float4 v4 = make_float4(0.f, 0.f, 0.f, 0.f);
    float m4 = -1e30f;
    if (q < 10) {
        float d2 = g_dinv[node]; d2 *= d2;
        uint2 su = ((const uint2*)(g_t2b + (size_t)node * 20))[q];
        float2 sa = unbf2(su.x), sb = unbf2(su.y);
        float4 bb = ((const float4*)b2)[q];
        v4.x = fmaf(sa.x, d2, acc.x) + bb.x;
        v4.y = fmaf(sa.y, d2, acc.y) + bb.y;
        v4.z = fmaf(sb.x, d2, acc.z) + bb.z;
        v4.w = fmaf(sb.y, d2, acc.w) + bb.w;
        m4 = fmaxf(fmaxf(v4.x, v4.y), fmaxf(v4.z, v4.w));
    }
#pragma unroll
    for (int o = 16; o; o >>= 1) m4 = fmaxf(m4, __shfl_xor_sync(0xffffffffu, m4, o));
    float s4 = 0.f;
    if (q < 10)
        s4 = expf(v4.x - m4) + expf(v4.y - m4) + expf(v4.z - m4) + expf(v4.w - m4);
#pragma unroll
    for (int o = 16; o; o >>= 1) s4 += __shfl_xor_sync(0xffffffffu, s4, o);
    float lse = m4 + logf(s4 * 0.5f);

    if (half == 0 && q < 10) {
        float4 r = make_float4(v4.x - lse, v4.y - lse, v4.z - lse, v4.w - lse);
        ((float4*)(out + (size_t)node * NOUT))[q] = r;
    }
}

// ---- launch -------------------------------------------------------------

extern "C" void kernel_launch(void* const* d_in, const int* in_sizes, int n_in,
                              void* d_out, int out_size) {
    const float* x   = (const float*)d_in[0];
    const int*   ei  = (const int*)d_in[1];
    const float* W1  = (const float*)d_in[2];
    const float* b1  = (const float*)d_in[3];
    const float* W2  = (const float*)d_in[4];
    const float* b2  = (const float*)d_in[5];
    float*       out = (float*)d_out;

    int n = in_sizes[0] / FEAT;   // 50000
    int E = in_sizes[1] / 2;      // 800000
    const int* src = ei;
    const int* dst = ei + E;
    int nb = (n + SCAN_BLK - 1) / SCAN_BLK;     // 196
    int ntiles = (n + TILE_R - 1) / TILE_R;     // 196

    const int G1_SMEM = (FEAT * W_STRIDE + 2 * TILE_R * XS_STRIDE) * sizeof(float);
    cudaFuncSetAttribute(gemm1_hist_kernel, cudaFuncAttributeMaxDynamicSharedMemorySize, G1_SMEM);

    void* pcc = nullptr;
    cudaGetSymbolAddress(&pcc, g_cnt);
    cudaMemsetAsync(pcc, 0, (NMAX + NBLKS) * sizeof(int));

    gemm1_hist_kernel<<<ntiles + HIST_BLKS, 256, G1_SMEM>>>(x, W1, dst, n, E, ntiles);
    scan_kernel<<<nb, SCAN_BLK>>>(n);
    fill_kernel<<<(E / 8 + 255) / 256, 256>>>(src, dst, E);
    agg1_kernel<<<(n * 32 + 255) / 256, 256>>>(b1, n);   // 4th kernel: profiled
    gemm2_kernel<<<(n + 255) / 256, 256>>>(W2, n);
    agg2_kernel<<<(n * 32 + 255) / 256, 256>>>(b2, out, n);
}